// round 14
// baseline (speedup 1.0000x reference)
#include <cuda_runtime.h>
#include <cuda_bf16.h>
#include <cuda_fp16.h>
#include <cstdint>

// Problem constants
#define BB 64
#define TT 512
#define BT (BB*TT)          // 32768
#define GIN 1024
#define HID 1024
#define H3  3072
#define NIN 512
#define KOUT 1536

// ----------------------------- scratch (device globals)
__device__ __half g_inp[(size_t)BT * GIN];                 // fp16 [emb|z]
__device__ float g_xproj[(size_t)BT * H3];                 // fp32 x-projection
__device__ __half g_hhi[(size_t)TT * BB * HID];            // [t][b][H] fp16 h
__device__ uint2 g_wihp[786432];                           // W_ih fp16 frag-packed
__device__ uint2 g_woutp[196608];                          // W_out fp16 frag-packed
__device__ unsigned g_flags[256 * 8];                      // flags (32B apart)

// ----------------------------- helpers
__device__ __forceinline__ void mma_f16(float acc[4], const unsigned a[4],
                                        unsigned b0, unsigned b1) {
    asm volatile(
        "mma.sync.aligned.m16n8k16.row.col.f32.f16.f16.f32 "
        "{%0,%1,%2,%3},{%4,%5,%6,%7},{%8,%9},{%0,%1,%2,%3};"
        : "+f"(acc[0]), "+f"(acc[1]), "+f"(acc[2]), "+f"(acc[3])
        : "r"(a[0]), "r"(a[1]), "r"(a[2]), "r"(a[3]), "r"(b0), "r"(b1));
}
__device__ __forceinline__ void ldsm4(unsigned r[4], uint32_t addr) {
    asm volatile("ldmatrix.sync.aligned.m8n8.x4.shared.b16 {%0,%1,%2,%3}, [%4];"
                 : "=r"(r[0]), "=r"(r[1]), "=r"(r[2]), "=r"(r[3]) : "r"(addr));
}
__device__ __forceinline__ uint32_t smem_u32(const void* p) {
    uint32_t a;
    asm("{ .reg .u64 t; cvta.to.shared.u64 t, %1; cvt.u32.u64 %0, t; }" : "=r"(a) : "l"(p));
    return a;
}
__device__ __forceinline__ void cpasync16(uint32_t dst, const void* src) {
    asm volatile("cp.async.cg.shared.global [%0], [%1], 16;" :: "r"(dst), "l"(src) : "memory");
}
__device__ __forceinline__ void cp_commit() {
    asm volatile("cp.async.commit_group;" ::: "memory");
}
__device__ __forceinline__ float sigmoidf(float v) { return 1.0f / (1.0f + expf(-v)); }
__device__ __forceinline__ uint32_t pk2h(__half a, __half b) {
    __half2 t(a, b);
    return *(uint32_t*)&t;
}

// ----------------------------- kernel: gather emb + concat z (fp16) ; reset flags
__global__ void build_inp_kernel(const int* __restrict__ x,
                                 const float* __restrict__ z,
                                 const float* __restrict__ emb) {
    size_t idx = (size_t)blockIdx.x * 256 + threadIdx.x;
    if (idx < 2048) g_flags[idx] = 0u;
    int m = (int)(idx >> 10);
    int k = (int)(idx & 1023);
    int b = m >> 9;
    float v;
    if (k < 512) v = emb[(size_t)x[m] * 512 + k];
    else         v = z[b * 512 + (k - 512)];
    g_inp[idx] = __float2half_rn(v);
}

// ----------------------------- kernel: pack weights into fp16 B-fragment order
__global__ void wpack_kernel(const float* __restrict__ Wih,
                             const float* __restrict__ Wout) {
    int idx = blockIdx.x * 256 + threadIdx.x;
    if (idx < 786432) {
        int kt = idx / 12288;
        int r  = idx % 12288;
        int strip = r >> 5, l = r & 31;
        int n = strip * 8 + (l >> 2);
        int k = kt * 16 + (l & 3) * 2;
        const float* wr = Wih + (size_t)n * GIN + k;
        uint2 v;
        v.x = pk2h(__float2half_rn(wr[0]), __float2half_rn(wr[1]));
        v.y = pk2h(__float2half_rn(wr[8]), __float2half_rn(wr[9]));
        g_wihp[idx] = v;
    } else {
        int j  = idx - 786432;
        int kt = j / 2048;
        int r  = j % 2048;
        int strip = r >> 5, l = r & 31;
        int n = strip * 8 + (l >> 2);
        int k = kt * 16 + (l & 3) * 2;
        const float* wr = Wout + (size_t)n * KOUT + k;
        uint2 v;
        v.x = pk2h(__float2half_rn(wr[0]), __float2half_rn(wr[1]));
        v.y = pk2h(__float2half_rn(wr[8]), __float2half_rn(wr[9]));
        g_woutp[j] = v;
    }
}

// ----------------------------- fp16 GEMM (R9-proven): C = A*W^T + bias, fp32 out
#define FSTG 34816              // A 128*144 + B 16384
template<bool CAT, bool TANH>
__global__ void __launch_bounds__(256, 2)
gemm_f16(const __half* __restrict__ Ainp, const __half* __restrict__ Ahid,
         const uint2* __restrict__ Wp, const float* __restrict__ bias,
         float* __restrict__ C, int N, int K) {
    extern __shared__ char smem[];
    const uint32_t sb = smem_u32(smem);
    const int tid  = threadIdx.x;
    const int lane = tid & 31;
    const int w    = tid >> 5;
    const int wm   = w >> 1;
    const int wn   = w & 1;
    const int bN   = blockIdx.x;
    const int bM   = blockIdx.y;
    const int S    = K >> 6;
    const int NSTRIP = N >> 3;

    float acc[2][8][4];
#pragma unroll
    for (int mt = 0; mt < 2; ++mt)
#pragma unroll
        for (int nt = 0; nt < 8; ++nt)
#pragma unroll
            for (int i = 0; i < 4; ++i) acc[mt][nt][i] = 0.f;

    auto stage = [&](int s) {
        const int k0 = s * 64;
        const uint32_t base = sb + (uint32_t)(s % 3) * FSTG;
#pragma unroll
        for (int it = 0; it < 4; ++it) {
            int o = tid + it * 256;
            int row = o >> 3, seg = o & 7;
            int m = bM * 128 + row;
            const __half* srcA;
            if (CAT) {
                if (k0 < 1024)
                    srcA = Ahid + ((size_t)(m & 511) * BB + (m >> 9)) * HID + k0 + seg * 8;
                else
                    srcA = Ainp + (size_t)m * 1024 + (k0 - 1024) + seg * 8;
            } else {
                srcA = Ainp + (size_t)m * 1024 + k0 + seg * 8;
            }
            cpasync16(base + row * 144 + seg * 16, srcA);
        }
#pragma unroll
        for (int it = 0; it < 4; ++it) {
            int o = tid + it * 256;
            int ktl = o >> 8, rem = o & 255;
            const char* src = (const char*)Wp
                + ((size_t)(s * 4 + ktl) * NSTRIP + bN * 16) * 256 + rem * 16;
            cpasync16(base + 18432 + ktl * 4096 + rem * 16, src);
        }
        cp_commit();
    };

    stage(0); stage(1); stage(2);

    for (int s = 0; s < S; ++s) {
        asm volatile("cp.async.wait_group 2;" ::: "memory");
        __syncthreads();
        const uint32_t As = sb + (uint32_t)(s % 3) * FSTG;
        const char* Bs = smem + (size_t)(s % 3) * FSTG + 18432;
        const uint32_t aAddr = As + (uint32_t)(wm * 32 + (lane & 15)) * 144 + (lane >> 4) * 16;
#pragma unroll
        for (int kt = 0; kt < 4; ++kt) {
            unsigned a[2][4];
            ldsm4(a[0], aAddr + kt * 32);
            ldsm4(a[1], aAddr + 16 * 144 + kt * 32);
#pragma unroll
            for (int nt = 0; nt < 8; ++nt) {
                uint2 Bv = *(const uint2*)(Bs + (size_t)kt * 4096
                           + (wn * 8 + nt) * 256 + lane * 8);
                mma_f16(acc[0][nt], a[0], Bv.x, Bv.y);
                mma_f16(acc[1][nt], a[1], Bv.x, Bv.y);
            }
        }
        __syncthreads();
        if (s + 3 < S) stage(s + 3);
        else cp_commit();
    }

#pragma unroll
    for (int nt = 0; nt < 8; ++nt) {
        int col = bN * 128 + wn * 64 + nt * 8 + 2 * (lane & 3);
        float b0 = bias[col], b1 = bias[col + 1];
#pragma unroll
        for (int mt = 0; mt < 2; ++mt) {
            int row = bM * 128 + wm * 32 + mt * 16 + (lane >> 2);
            float v00 = acc[mt][nt][0] + b0;
            float v01 = acc[mt][nt][1] + b1;
            float v10 = acc[mt][nt][2] + b0;
            float v11 = acc[mt][nt][3] + b1;
            if (TANH) { v00 = tanhf(v00); v01 = tanhf(v01); v10 = tanhf(v10); v11 = tanhf(v11); }
            *(float2*)&C[(size_t)row * N + col]       = make_float2(v00, v01);
            *(float2*)&C[(size_t)(row + 8) * N + col] = make_float2(v10, v11);
        }
    }
}

// ----------------------------- GRU persistent kernel v6 (2 CTAs/SM)
// 4 groups x 64 CTAs (256 total, 2/SM co-resident); group owns 16 batch rows;
// CTA owns 16 hidden cols. 6 warps (192 thr): warp = (gate, ch); N=8, K=1024.
// W slice 48x1024 fp16 B-frags = 96KB. h(t-1): 8 chunks of k=128, 3-buffer
// cp.async ring (R9-proven flow). Preact [3][16][20]f aliases buffer 2
// (last read iter 5, ordered before sync(6) <= sync(7) < preact writes).
// Co-residency of 2 CTAs from different groups overlaps poll/staging stalls.
#define SM_W 0u
#define SM_A 98304u
#define CBUF 4352u
#define SM_P (98304u + 2u * 4352u)
#define SMEM_GRU 111360

__global__ void __launch_bounds__(192, 2)
gru_kernel(const float* __restrict__ Whh, const float* __restrict__ bhh,
           const int* __restrict__ x, const float* __restrict__ xproj,
           __half* __restrict__ hhi) {
    extern __shared__ char smem[];
    const uint32_t sb = smem_u32(smem);
    const int tid   = threadIdx.x;
    const int wid   = tid >> 5;
    const int lane  = tid & 31;
    const int group = blockIdx.x >> 6;        // 0..3
    const int b0    = group * 16;
    const int jc    = (blockIdx.x & 63) * 16; // 16 hidden cols
    const int gate  = wid >> 1;               // 0..2
    const int ch    = wid & 1;                // col-half (8 cols)
    const int strip = gate * 2 + ch;

    // ---- one-time: pack W_hh slice (48 rows x 1024) into fp16 B-fragments
    // layout: [64 kt][6 strips][32 lanes x uint2]
    for (int u = tid; u < 12288; u += 192) {
        int kt = u / 192;
        int rem = u % 192;
        int st = rem >> 5, l = rem & 31;
        int g = st >> 1, co = (st & 1) * 8;
        int n = jc + co + (l >> 2);
        int k = kt * 16 + (l & 3) * 2;
        const float* wr = Whh + (size_t)(g * 1024 + n) * 1024;
        uint2 v;
        v.x = pk2h(__float2half_rn(wr[k]),     __float2half_rn(wr[k + 1]));
        v.y = pk2h(__float2half_rn(wr[k + 8]), __float2half_rn(wr[k + 9]));
        *(uint2*)(smem + SM_W + (size_t)(kt * 6 + st) * 256 + (size_t)l * 8) = v;
    }
    __syncthreads();

    // ---- epilogue thread setup: tid<64, each owns (batch row, 4 cols)
    const int erow = tid >> 2;                // 0..15
    const int ec4  = (tid & 3) * 4;           // 0,4,8,12
    const int eb   = b0 + erow;
    float hp[4] = {0.f, 0.f, 0.f, 0.f};
    float br_[4], bu_[4], bn_[4];
    if (tid < 64) {
#pragma unroll
        for (int j = 0; j < 4; ++j) {
            br_[j] = bhh[jc + ec4 + j];
            bu_[j] = bhh[1024 + jc + ec4 + j];
            bn_[j] = bhh[2048 + jc + ec4 + j];
        }
    }

    for (int t = 0; t < TT; ++t) {
        // ---- epilogue operand prefetch (fp32 xproj)
        int xtok = 0;
        float4 xr, xu, xn;
        if (tid < 64) {
            xtok = x[eb * TT + t];
            const float* xb = xproj + ((size_t)eb * TT + t) * H3 + jc + ec4;
            xr = *(const float4*)xb;
            xu = *(const float4*)(xb + 1024);
            xn = *(const float4*)(xb + 2048);
        }

        if (t > 0) {
            // group-flag wait: warp 0 only; 64 flags, 2 per lane
            if (wid == 0) {
                const unsigned* f0 = &g_flags[(group * 64 + lane) * 8];
                const unsigned* f1 = &g_flags[(group * 64 + 32 + lane) * 8];
                for (;;) {
                    unsigned v0, v1;
                    asm volatile("ld.acquire.gpu.global.u32 %0, [%1];" : "=r"(v0) : "l"(f0));
                    asm volatile("ld.acquire.gpu.global.u32 %0, [%1];" : "=r"(v1) : "l"(f1));
                    if (__all_sync(0xffffffffu,
                                   (v0 >= (unsigned)t) && (v1 >= (unsigned)t))) break;
                    __nanosleep(20);
                }
            }
            __syncthreads();

            // stage chunk i (k = i*128..+128) into buffer i%3
            auto stage = [&](int i) {
                {
                    int idx = tid;                       // 0..191
                    int row = idx >> 4, seg = idx & 15;
                    const __half* src = hhi + ((size_t)(t - 1) * BB + b0 + row) * HID
                                      + i * 128 + seg * 8;
                    cpasync16(sb + SM_A + (uint32_t)(i % 3) * CBUF
                              + (uint32_t)row * 272 + seg * 16, src);
                }
                if (tid < 64) {
                    int idx = tid + 192;                 // 192..255
                    int row = idx >> 4, seg = idx & 15;
                    const __half* src = hhi + ((size_t)(t - 1) * BB + b0 + row) * HID
                                      + i * 128 + seg * 8;
                    cpasync16(sb + SM_A + (uint32_t)(i % 3) * CBUF
                              + (uint32_t)row * 272 + seg * 16, src);
                }
                cp_commit();
            };

            float acc[2][4] = {};       // [parity][4]
            stage(0); stage(1);
            for (int i = 0; i < 8; ++i) {
                if (i < 7) asm volatile("cp.async.wait_group 1;" ::: "memory");
                else       asm volatile("cp.async.wait_group 0;" ::: "memory");
                __syncthreads();
                if (i < 6) stage(i + 2);
                const uint32_t ah = sb + SM_A + (uint32_t)(i % 3) * CBUF
                                  + (uint32_t)(lane & 15) * 272 + (lane >> 4) * 16;
#pragma unroll
                for (int kt = 0; kt < 8; ++kt) {
                    unsigned aF[4];
                    ldsm4(aF, ah + kt * 32);
                    uint2 B = *(const uint2*)(smem + SM_W
                              + (size_t)(((i * 8 + kt) * 6) + strip) * 256
                              + (size_t)lane * 8);
                    mma_f16(acc[kt & 1], aF, B.x, B.y);
                }
            }
            // preact write: [gate][16 rows][20 floats], cols = ch*8 + 2*(lane&3)
            // (aliases buffer 2: last read iter 5 < sync(6) <= sync(7) < here)
            {
                int r   = lane >> 2;
                int col = ch * 8 + 2 * (lane & 3);
                float d0 = acc[0][0] + acc[1][0];
                float d1 = acc[0][1] + acc[1][1];
                float d2 = acc[0][2] + acc[1][2];
                float d3 = acc[0][3] + acc[1][3];
                *(float2*)(smem + SM_P + (size_t)((gate * 16 + r) * 20 + col) * 4)
                    = make_float2(d0, d1);
                *(float2*)(smem + SM_P + (size_t)((gate * 16 + r + 8) * 20 + col) * 4)
                    = make_float2(d2, d3);
            }
        }
        __syncthreads();

        // ---- epilogue: 64 threads, (row, 4 cols) each
        if (tid < 64) {
            float dr[4] = {}, du[4] = {}, dn[4] = {};
            if (t > 0) {
#pragma unroll
                for (int g = 0; g < 3; ++g) {
                    float4 v = *(const float4*)(smem + SM_P
                               + (size_t)((g * 16 + erow) * 20 + ec4) * 4);
                    float* d = (g == 0) ? dr : (g == 1 ? du : dn);
                    d[0] = v.x; d[1] = v.y; d[2] = v.z; d[3] = v.w;
                }
            }
            float xrv[4] = {xr.x, xr.y, xr.z, xr.w};
            float xuv[4] = {xu.x, xu.y, xu.z, xu.w};
            float xnv[4] = {xn.x, xn.y, xn.z, xn.w};
            const bool msk = (xtok == 0);   // PAD
            float hv[4];
#pragma unroll
            for (int j = 0; j < 4; ++j) {
                float rr = sigmoidf(xrv[j] + dr[j] + br_[j]);
                float uu = sigmoidf(xuv[j] + du[j] + bu_[j]);
                float nn = tanhf(xnv[j] + rr * (dn[j] + bn_[j]));
                float h  = (1.f - uu) * nn + uu * hp[j];
                hv[j] = msk ? hp[j] : h;
                hp[j] = hv[j];
            }
            uint2 uh;
            uh.x = pk2h(__float2half_rn(hv[0]), __float2half_rn(hv[1]));
            uh.y = pk2h(__float2half_rn(hv[2]), __float2half_rn(hv[3]));
            *(uint2*)(hhi + ((size_t)t * BB + eb) * HID + jc + ec4) = uh;
        }
        __syncthreads();

        // ---- release (bar gives intra-CTA HB; gpu-scope release publishes)
        if (tid == 0) {
            asm volatile("st.release.gpu.global.u32 [%0], %1;"
                         :: "l"(&g_flags[blockIdx.x * 8]), "r"((unsigned)(t + 1)) : "memory");
        }
    }
}

// ----------------------------- launch
extern "C" void kernel_launch(void* const* d_in, const int* in_sizes, int n_in,
                              void* d_out, int out_size) {
    const int*   x     = (const int*)d_in[0];
    const float* z     = (const float*)d_in[1];
    const float* emb   = (const float*)d_in[2];
    const float* W_ih  = (const float*)d_in[3];
    const float* b_ih  = (const float*)d_in[4];
    const float* W_hh  = (const float*)d_in[5];
    const float* b_hh  = (const float*)d_in[6];
    const float* W_out = (const float*)d_in[7];
    const float* b_out = (const float*)d_in[8];
    float* out = (float*)d_out;

    float *xproj_p;
    __half *inp_p, *hhi_p;
    uint2 *wihp_p, *woutp_p;
    cudaGetSymbolAddress((void**)&inp_p,   g_inp);
    cudaGetSymbolAddress((void**)&xproj_p, g_xproj);
    cudaGetSymbolAddress((void**)&hhi_p,   g_hhi);
    cudaGetSymbolAddress((void**)&wihp_p,  g_wihp);
    cudaGetSymbolAddress((void**)&woutp_p, g_woutp);

    // 1. build inp (fp16 emb||z), reset barrier flags
    build_inp_kernel<<<(unsigned)((size_t)BT * GIN / 256), 256>>>(x, z, emb);

    // 2. pack weights into fp16 fragment order
    wpack_kernel<<<3840, 256>>>(W_ih, W_out);

    // 3. x_proj = inp @ W_ih^T + b_ih   [32768 x 3072], K=1024, fp32 out
    {
        cudaFuncSetAttribute(gemm_f16<false, false>,
                             cudaFuncAttributeMaxDynamicSharedMemorySize, 3 * FSTG);
        dim3 grid(H3 / 128, BT / 128);
        gemm_f16<false, false><<<grid, 256, 3 * FSTG>>>(
            inp_p, nullptr, wihp_p, b_ih, xproj_p, H3, GIN);
    }

    // 4. GRU recurrence: 4 groups x 64 CTAs, 2 CTAs/SM co-resident
    {
        cudaFuncSetAttribute(gru_kernel,
                             cudaFuncAttributeMaxDynamicSharedMemorySize, SMEM_GRU);
        gru_kernel<<<256, 192, SMEM_GRU>>>(W_hh, b_hh, x, xproj_p, hhi_p);
    }

    // 5. logits = tanh([hidden|emb] @ W_out^T + b_out)   [32768 x 512], fp32 out
    {
        cudaFuncSetAttribute(gemm_f16<true, true>,
                             cudaFuncAttributeMaxDynamicSharedMemorySize, 3 * FSTG);
        dim3 grid(NIN / 128, BT / 128);
        gemm_f16<true, true><<<grid, 256, 3 * FSTG>>>(
            inp_p, hhi_p, woutp_p, b_out, out, NIN, KOUT);
    }
}

// round 15
// speedup vs baseline: 1.2600x; 1.2600x over previous
#include <cuda_runtime.h>
#include <cuda_bf16.h>
#include <cuda_fp16.h>
#include <cstdint>

// Problem constants
#define BB 64
#define TT 512
#define BT (BB*TT)          // 32768
#define GIN 1024
#define HID 1024
#define H3  3072
#define NIN 512
#define KOUT 1536

// ----------------------------- scratch (device globals)
__device__ __half g_inp[(size_t)BT * GIN];                 // fp16 [emb|z]
__device__ __half g_zpad[(size_t)128 * 1024];              // fp16 z zero-padded [128][1024]
__device__ float g_zproj[(size_t)128 * H3];                // fp32 z-projection + b_ih
__device__ float g_xproj[(size_t)BT * H3];                 // fp32 x-projection
__device__ __half g_hhi[(size_t)TT * BB * HID];            // [t][b][H] fp16 h
__device__ uint2 g_wihp[786432];                           // W_ih fp16 frag-packed
__device__ uint2 g_woutp[196608];                          // W_out fp16 frag-packed
__device__ unsigned g_flags[128 * 8];                      // flags (32B apart)

// ----------------------------- helpers
__device__ __forceinline__ void mma_f16(float acc[4], const unsigned a[4],
                                        unsigned b0, unsigned b1) {
    asm volatile(
        "mma.sync.aligned.m16n8k16.row.col.f32.f16.f16.f32 "
        "{%0,%1,%2,%3},{%4,%5,%6,%7},{%8,%9},{%0,%1,%2,%3};"
        : "+f"(acc[0]), "+f"(acc[1]), "+f"(acc[2]), "+f"(acc[3])
        : "r"(a[0]), "r"(a[1]), "r"(a[2]), "r"(a[3]), "r"(b0), "r"(b1));
}
__device__ __forceinline__ void ldsm4(unsigned r[4], uint32_t addr) {
    asm volatile("ldmatrix.sync.aligned.m8n8.x4.shared.b16 {%0,%1,%2,%3}, [%4];"
                 : "=r"(r[0]), "=r"(r[1]), "=r"(r[2]), "=r"(r[3]) : "r"(addr));
}
__device__ __forceinline__ uint32_t smem_u32(const void* p) {
    uint32_t a;
    asm("{ .reg .u64 t; cvta.to.shared.u64 t, %1; cvt.u32.u64 %0, t; }" : "=r"(a) : "l"(p));
    return a;
}
__device__ __forceinline__ void cpasync16(uint32_t dst, const void* src) {
    asm volatile("cp.async.cg.shared.global [%0], [%1], 16;" :: "r"(dst), "l"(src) : "memory");
}
__device__ __forceinline__ void cp_commit() {
    asm volatile("cp.async.commit_group;" ::: "memory");
}
__device__ __forceinline__ float sigmoidf(float v) { return 1.0f / (1.0f + expf(-v)); }
__device__ __forceinline__ uint32_t pk2h(__half a, __half b) {
    __half2 t(a, b);
    return *(uint32_t*)&t;
}

// ----------------------------- kernel: gather emb + concat z (fp16), fill zpad,
// reset flags
__global__ void build_inp_kernel(const int* __restrict__ x,
                                 const float* __restrict__ z,
                                 const float* __restrict__ emb) {
    size_t idx = (size_t)blockIdx.x * 256 + threadIdx.x;
    if (idx < 1024) g_flags[idx] = 0u;
    if (idx < 131072) {   // zpad [128][1024]: rows<64, cols<512 = z; else 0
        int row = (int)(idx >> 10);
        int col = (int)(idx & 1023);
        float v = (row < 64 && col < 512) ? z[row * 512 + col] : 0.f;
        g_zpad[idx] = __float2half_rn(v);
    }
    int m = (int)(idx >> 10);
    int k = (int)(idx & 1023);
    int b = m >> 9;
    float v;
    if (k < 512) v = emb[(size_t)x[m] * 512 + k];
    else         v = z[b * 512 + (k - 512)];
    g_inp[idx] = __float2half_rn(v);
}

// ----------------------------- kernel: pack weights into fp16 B-fragment order
__global__ void wpack_kernel(const float* __restrict__ Wih,
                             const float* __restrict__ Wout) {
    int idx = blockIdx.x * 256 + threadIdx.x;
    if (idx < 786432) {
        int kt = idx / 12288;
        int r  = idx % 12288;
        int strip = r >> 5, l = r & 31;
        int n = strip * 8 + (l >> 2);
        int k = kt * 16 + (l & 3) * 2;
        const float* wr = Wih + (size_t)n * GIN + k;
        uint2 v;
        v.x = pk2h(__float2half_rn(wr[0]), __float2half_rn(wr[1]));
        v.y = pk2h(__float2half_rn(wr[8]), __float2half_rn(wr[9]));
        g_wihp[idx] = v;
    } else {
        int j  = idx - 786432;
        int kt = j / 2048;
        int r  = j % 2048;
        int strip = r >> 5, l = r & 31;
        int n = strip * 8 + (l >> 2);
        int k = kt * 16 + (l & 3) * 2;
        const float* wr = Wout + (size_t)n * KOUT + k;
        uint2 v;
        v.x = pk2h(__float2half_rn(wr[0]), __float2half_rn(wr[1]));
        v.y = pk2h(__float2half_rn(wr[8]), __float2half_rn(wr[9]));
        g_woutp[j] = v;
    }
}

// ----------------------------- fp16 GEMM: C = A*W^T + bias, fp32 out
// ZROW: bias indexed per batch row (zproj[bM/4][col]) instead of bias[col].
#define FSTG 34816              // A 128*144 + B 16384
template<bool CAT, bool TANH, bool ZROW>
__global__ void __launch_bounds__(256, 2)
gemm_f16(const __half* __restrict__ Ainp, const __half* __restrict__ Ahid,
         const uint2* __restrict__ Wp, const float* __restrict__ bias,
         float* __restrict__ C, int N, int K) {
    extern __shared__ char smem[];
    const uint32_t sb = smem_u32(smem);
    const int tid  = threadIdx.x;
    const int lane = tid & 31;
    const int w    = tid >> 5;
    const int wm   = w >> 1;
    const int wn   = w & 1;
    const int bN   = blockIdx.x;
    const int bM   = blockIdx.y;
    const int S    = K >> 6;
    const int NSTRIP = N >> 3;

    float acc[2][8][4];
#pragma unroll
    for (int mt = 0; mt < 2; ++mt)
#pragma unroll
        for (int nt = 0; nt < 8; ++nt)
#pragma unroll
            for (int i = 0; i < 4; ++i) acc[mt][nt][i] = 0.f;

    auto stage = [&](int s) {
        const int k0 = s * 64;
        const uint32_t base = sb + (uint32_t)(s % 3) * FSTG;
#pragma unroll
        for (int it = 0; it < 4; ++it) {
            int o = tid + it * 256;
            int row = o >> 3, seg = o & 7;
            int m = bM * 128 + row;
            const __half* srcA;
            if (CAT) {
                if (k0 < 1024)
                    srcA = Ahid + ((size_t)(m & 511) * BB + (m >> 9)) * HID + k0 + seg * 8;
                else
                    srcA = Ainp + (size_t)m * 1024 + (k0 - 1024) + seg * 8;
            } else {
                srcA = Ainp + (size_t)m * 1024 + k0 + seg * 8;
            }
            cpasync16(base + row * 144 + seg * 16, srcA);
        }
#pragma unroll
        for (int it = 0; it < 4; ++it) {
            int o = tid + it * 256;
            int ktl = o >> 8, rem = o & 255;
            const char* src = (const char*)Wp
                + ((size_t)(s * 4 + ktl) * NSTRIP + bN * 16) * 256 + rem * 16;
            cpasync16(base + 18432 + ktl * 4096 + rem * 16, src);
        }
        cp_commit();
    };

    stage(0); stage(1); stage(2);

    for (int s = 0; s < S; ++s) {
        asm volatile("cp.async.wait_group 2;" ::: "memory");
        __syncthreads();
        const uint32_t As = sb + (uint32_t)(s % 3) * FSTG;
        const char* Bs = smem + (size_t)(s % 3) * FSTG + 18432;
        const uint32_t aAddr = As + (uint32_t)(wm * 32 + (lane & 15)) * 144 + (lane >> 4) * 16;
#pragma unroll
        for (int kt = 0; kt < 4; ++kt) {
            unsigned a[2][4];
            ldsm4(a[0], aAddr + kt * 32);
            ldsm4(a[1], aAddr + 16 * 144 + kt * 32);
#pragma unroll
            for (int nt = 0; nt < 8; ++nt) {
                uint2 Bv = *(const uint2*)(Bs + (size_t)kt * 4096
                           + (wn * 8 + nt) * 256 + lane * 8);
                mma_f16(acc[0][nt], a[0], Bv.x, Bv.y);
                mma_f16(acc[1][nt], a[1], Bv.x, Bv.y);
            }
        }
        __syncthreads();
        if (s + 3 < S) stage(s + 3);
        else cp_commit();
    }

    // bias row: ZROW -> per-batch-row vector (whole 128-row block is one b)
    const float* brow = ZROW ? (bias + (size_t)(bM >> 2) * N) : bias;
#pragma unroll
    for (int nt = 0; nt < 8; ++nt) {
        int col = bN * 128 + wn * 64 + nt * 8 + 2 * (lane & 3);
        float b0 = brow[col], b1 = brow[col + 1];
#pragma unroll
        for (int mt = 0; mt < 2; ++mt) {
            int row = bM * 128 + wm * 32 + mt * 16 + (lane >> 2);
            float v00 = acc[mt][nt][0] + b0;
            float v01 = acc[mt][nt][1] + b1;
            float v10 = acc[mt][nt][2] + b0;
            float v11 = acc[mt][nt][3] + b1;
            if (TANH) { v00 = tanhf(v00); v01 = tanhf(v01); v10 = tanhf(v10); v11 = tanhf(v11); }
            *(float2*)&C[(size_t)row * N + col]       = make_float2(v00, v01);
            *(float2*)&C[(size_t)(row + 8) * N + col] = make_float2(v10, v11);
        }
    }
}

// ----------------------------- GRU persistent kernel (EXACT R9 — best known)
// 4 groups x 32 CTAs; group owns 16 batch rows; CTA owns 32 hidden cols.
// 12 warps: warp = (gate, kh, ch); M=16, N=16, K=512 per warp.
// 4 chunk-pairs of k=128, 3-buffer cp.async pipeline.
// Preact aliases buffer 1: its last A-read (iter 1) precedes sync(3), which
// precedes all preact writes -> race-free.
#define SM_W 0u
#define SM_A 196608u
#define PBUF 8704u
#define SM_P (196608u + 8704u)
#define SMEM_GRU 222720

__global__ void __launch_bounds__(384, 1)
gru_kernel(const float* __restrict__ Whh, const float* __restrict__ bhh,
           const int* __restrict__ x, const float* __restrict__ xproj,
           __half* __restrict__ hhi) {
    extern __shared__ char smem[];
    const uint32_t sb = smem_u32(smem);
    const int tid   = threadIdx.x;
    const int wid   = tid >> 5;
    const int lane  = tid & 31;
    const int group = blockIdx.x >> 5;        // 0..3
    const int b0    = group * 16;
    const int jc    = (blockIdx.x & 31) * 32; // 32 hidden cols
    const int gate  = wid >> 2;               // 0..2
    const int kh    = (wid >> 1) & 1;         // k-half
    const int ch    = wid & 1;                // col-half
    const int s0    = gate * 4 + ch * 2;      // W strip ids
    const int s1    = s0 + 1;

    // ---- one-time: pack W_hh slice (96 rows x 1024) into fp16 B-fragments
    for (int u = tid; u < 24576; u += 384) {
        int kt = u / 384;
        int rem = u % 384;
        int strip = rem >> 5, l = rem & 31;
        int g = strip >> 2, co = (strip & 3) * 8;
        int n = jc + co + (l >> 2);
        int k = kt * 16 + (l & 3) * 2;
        const float* wr = Whh + (size_t)(g * 1024 + n) * 1024;
        uint2 v;
        v.x = pk2h(__float2half_rn(wr[k]),     __float2half_rn(wr[k + 1]));
        v.y = pk2h(__float2half_rn(wr[k + 8]), __float2half_rn(wr[k + 9]));
        *(uint2*)(smem + SM_W + (size_t)(kt * 12 + strip) * 256 + (size_t)l * 8) = v;
    }
    __syncthreads();

    // ---- epilogue thread setup: tid<128, each owns (batch row, 4 cols)
    const int erow = tid >> 3;                // 0..15
    const int ec4  = (tid & 7) * 4;           // 0,4,..28
    const int eb   = b0 + erow;
    float hp[4] = {0.f, 0.f, 0.f, 0.f};
    float br_[4], bu_[4], bn_[4];
    if (tid < 128) {
#pragma unroll
        for (int j = 0; j < 4; ++j) {
            br_[j] = bhh[jc + ec4 + j];
            bu_[j] = bhh[1024 + jc + ec4 + j];
            bn_[j] = bhh[2048 + jc + ec4 + j];
        }
    }

    for (int t = 0; t < TT; ++t) {
        // ---- epilogue operand prefetch (fp32 xproj)
        int xtok = 0;
        float4 xr, xu, xn;
        if (tid < 128) {
            xtok = x[eb * TT + t];
            const float* xb = xproj + ((size_t)eb * TT + t) * H3 + jc + ec4;
            xr = *(const float4*)xb;
            xu = *(const float4*)(xb + 1024);
            xn = *(const float4*)(xb + 2048);
        }

        if (t > 0) {
            // coarse group-flag wait: warp 0 only, one flag per lane
            if (wid == 0) {
                const unsigned* f = &g_flags[(group * 32 + lane) * 8];
                for (;;) {
                    unsigned v;
                    asm volatile("ld.acquire.gpu.global.u32 %0, [%1];" : "=r"(v) : "l"(f));
                    if (__all_sync(0xffffffffu, v >= (unsigned)t)) break;
                    __nanosleep(20);
                }
            }
            __syncthreads();

            // stage pair i: chunks {i, i+4} of h(t-1)
            auto stage = [&](int i) {
                if (tid < 256) {
                    int row = tid >> 4, seg = tid & 15;
                    const __half* src = hhi + ((size_t)(t - 1) * BB + b0 + row) * HID + seg * 8;
                    uint32_t dst = sb + SM_A + (uint32_t)(i % 3) * PBUF
                                 + (uint32_t)row * 272 + seg * 16;
                    cpasync16(dst,        src + i * 128);
                    cpasync16(dst + 4352, src + (i + 4) * 128);
                }
                cp_commit();
            };

            float acc[2][2][4] = {};   // [ntile][parity][4]
            stage(0); stage(1);
            for (int i = 0; i < 4; ++i) {
                if (i < 3) asm volatile("cp.async.wait_group 1;" ::: "memory");
                else       asm volatile("cp.async.wait_group 0;" ::: "memory");
                __syncthreads();
                if (i < 2) stage(i + 2);
                const uint32_t ah = sb + SM_A + (uint32_t)(i % 3) * PBUF
                                  + (uint32_t)kh * 4352
                                  + (uint32_t)(lane & 15) * 272 + (lane >> 4) * 16;
                const int ktg0 = kh * 32 + i * 8;
#pragma unroll
                for (int kt = 0; kt < 8; ++kt) {
                    unsigned aF[4];
                    ldsm4(aF, ah + kt * 32);
                    uint2 B0 = *(const uint2*)(smem + SM_W
                               + (size_t)((ktg0 + kt) * 12 + s0) * 256 + (size_t)lane * 8);
                    uint2 B1 = *(const uint2*)(smem + SM_W
                               + (size_t)((ktg0 + kt) * 12 + s1) * 256 + (size_t)lane * 8);
                    const int p = kt & 1;
                    mma_f16(acc[0][p], aF, B0.x, B0.y);
                    mma_f16(acc[1][p], aF, B1.x, B1.y);
                }
            }
            // preact partial write: [(gate*2+kh)*16 + r][36 floats]
            {
                int r  = lane >> 2;
                int cb = ch * 16 + 2 * (lane & 3);
#pragma unroll
                for (int nt = 0; nt < 2; ++nt) {
                    float d0 = acc[nt][0][0] + acc[nt][1][0];
                    float d1 = acc[nt][0][1] + acc[nt][1][1];
                    float d2 = acc[nt][0][2] + acc[nt][1][2];
                    float d3 = acc[nt][0][3] + acc[nt][1][3];
                    int col = cb + nt * 8;
                    *(float2*)(smem + SM_P
                        + (size_t)(((gate * 2 + kh) * 16 + r) * 36 + col) * 4)
                        = make_float2(d0, d1);
                    *(float2*)(smem + SM_P
                        + (size_t)(((gate * 2 + kh) * 16 + r + 8) * 36 + col) * 4)
                        = make_float2(d2, d3);
                }
            }
        }
        __syncthreads();

        // ---- epilogue: 128 threads, (row, 4 cols) each
        if (tid < 128) {
            float dr[4] = {}, du[4] = {}, dn[4] = {};
            if (t > 0) {
#pragma unroll
                for (int g = 0; g < 3; ++g) {
                    float4 a = *(const float4*)(smem + SM_P
                               + (size_t)((g * 2 + 0) * 16 + erow) * 144 + ec4 * 4);
                    float4 b = *(const float4*)(smem + SM_P
                               + (size_t)((g * 2 + 1) * 16 + erow) * 144 + ec4 * 4);
                    float* d = (g == 0) ? dr : (g == 1 ? du : dn);
                    d[0] = a.x + b.x; d[1] = a.y + b.y;
                    d[2] = a.z + b.z; d[3] = a.w + b.w;
                }
            }
            float xrv[4] = {xr.x, xr.y, xr.z, xr.w};
            float xuv[4] = {xu.x, xu.y, xu.z, xu.w};
            float xnv[4] = {xn.x, xn.y, xn.z, xn.w};
            const bool msk = (xtok == 0);   // PAD
            float hv[4];
#pragma unroll
            for (int j = 0; j < 4; ++j) {
                float rr = sigmoidf(xrv[j] + dr[j] + br_[j]);
                float uu = sigmoidf(xuv[j] + du[j] + bu_[j]);
                float nn = tanhf(xnv[j] + rr * (dn[j] + bn_[j]));
                float h  = (1.f - uu) * nn + uu * hp[j];
                hv[j] = msk ? hp[j] : h;
                hp[j] = hv[j];
            }
            uint2 uh;
            uh.x = pk2h(__float2half_rn(hv[0]), __float2half_rn(hv[1]));
            uh.y = pk2h(__float2half_rn(hv[2]), __float2half_rn(hv[3]));
            *(uint2*)(hhi + ((size_t)t * BB + eb) * HID + jc + ec4) = uh;
        }
        __syncthreads();

        // ---- release (bar gives intra-CTA HB; gpu-scope release publishes)
        if (tid == 0) {
            asm volatile("st.release.gpu.global.u32 [%0], %1;"
                         :: "l"(&g_flags[blockIdx.x * 8]), "r"((unsigned)(t + 1)) : "memory");
        }
    }
}

// ----------------------------- launch
extern "C" void kernel_launch(void* const* d_in, const int* in_sizes, int n_in,
                              void* d_out, int out_size) {
    const int*   x     = (const int*)d_in[0];
    const float* z     = (const float*)d_in[1];
    const float* emb   = (const float*)d_in[2];
    const float* W_ih  = (const float*)d_in[3];
    const float* b_ih  = (const float*)d_in[4];
    const float* W_hh  = (const float*)d_in[5];
    const float* b_hh  = (const float*)d_in[6];
    const float* W_out = (const float*)d_in[7];
    const float* b_out = (const float*)d_in[8];
    float* out = (float*)d_out;

    float *xproj_p, *zproj_p;
    __half *inp_p, *zpad_p, *hhi_p;
    uint2 *wihp_p, *woutp_p;
    cudaGetSymbolAddress((void**)&inp_p,   g_inp);
    cudaGetSymbolAddress((void**)&zpad_p,  g_zpad);
    cudaGetSymbolAddress((void**)&zproj_p, g_zproj);
    cudaGetSymbolAddress((void**)&xproj_p, g_xproj);
    cudaGetSymbolAddress((void**)&hhi_p,   g_hhi);
    cudaGetSymbolAddress((void**)&wihp_p,  g_wihp);
    cudaGetSymbolAddress((void**)&woutp_p, g_woutp);

    // 1. build inp (fp16 emb||z), zpad, reset barrier flags
    build_inp_kernel<<<(unsigned)((size_t)BT * GIN / 256), 256>>>(x, z, emb);

    // 2. pack weights into fp16 fragment order
    wpack_kernel<<<3840, 256>>>(W_ih, W_out);

    // 3a. zproj = z @ W_ih[:,512:]^T + b_ih   [64(pad 128) x 3072], K=512
    {
        cudaFuncSetAttribute(gemm_f16<false, false, false>,
                             cudaFuncAttributeMaxDynamicSharedMemorySize, 3 * FSTG);
        dim3 grid(H3 / 128, 1);
        gemm_f16<false, false, false><<<grid, 256, 3 * FSTG>>>(
            zpad_p, nullptr, wihp_p + 393216, b_ih, zproj_p, H3, 512);
    }

    // 3b. xproj = emb @ W_ih[:,:512]^T + zproj[b]   [32768 x 3072], K=512
    {
        cudaFuncSetAttribute(gemm_f16<false, false, true>,
                             cudaFuncAttributeMaxDynamicSharedMemorySize, 3 * FSTG);
        dim3 grid(H3 / 128, BT / 128);
        gemm_f16<false, false, true><<<grid, 256, 3 * FSTG>>>(
            inp_p, nullptr, wihp_p, zproj_p, xproj_p, H3, 512);
    }

    // 4. GRU recurrence: 4 independent batch groups x 32 CTAs (R9-exact)
    {
        cudaFuncSetAttribute(gru_kernel,
                             cudaFuncAttributeMaxDynamicSharedMemorySize, SMEM_GRU);
        gru_kernel<<<128, 384, SMEM_GRU>>>(W_hh, b_hh, x, xproj_p, hhi_p);
    }

    // 5. logits = tanh([hidden|emb] @ W_out^T + b_out)   [32768 x 512], K=1536
    {
        cudaFuncSetAttribute(gemm_f16<true, true, false>,
                             cudaFuncAttributeMaxDynamicSharedMemorySize, 3 * FSTG);
        dim3 grid(NIN / 128, BT / 128);
        gemm_f16<true, true, false><<<grid, 256, 3 * FSTG>>>(
            inp_p, hhi_p, woutp_p, b_out, out, NIN, KOUT);
    }
}

// round 16
// speedup vs baseline: 1.2748x; 1.0118x over previous
#include <cuda_runtime.h>
#include <cuda_bf16.h>
#include <cuda_fp16.h>
#include <cstdint>

// Problem constants
#define BB 64
#define TT 512
#define BT (BB*TT)          // 32768
#define GIN 1024
#define HID 1024
#define H3  3072
#define NIN 512
#define KOUT 1536

// ----------------------------- scratch (device globals)
__device__ __half g_inp[(size_t)BT * GIN];                 // fp16 [emb | unused]
__device__ __half g_zpad[(size_t)128 * 1024];              // fp16 z zero-padded [128][1024]
__device__ float g_zproj[(size_t)128 * H3];                // fp32 z-projection + b_ih
__device__ float g_xproj[(size_t)BT * H3];                 // fp32 x-projection
__device__ __half g_hhi[(size_t)TT * BB * HID];            // [t][b][H] fp16 h
__device__ uint2 g_wihp[786432];                           // W_ih fp16 frag-packed
__device__ uint2 g_woutp[196608];                          // W_out fp16 frag-packed
__device__ unsigned g_flags[128 * 8];                      // flags (32B apart)

// ----------------------------- helpers
__device__ __forceinline__ void mma_f16(float acc[4], const unsigned a[4],
                                        unsigned b0, unsigned b1) {
    asm volatile(
        "mma.sync.aligned.m16n8k16.row.col.f32.f16.f16.f32 "
        "{%0,%1,%2,%3},{%4,%5,%6,%7},{%8,%9},{%0,%1,%2,%3};"
        : "+f"(acc[0]), "+f"(acc[1]), "+f"(acc[2]), "+f"(acc[3])
        : "r"(a[0]), "r"(a[1]), "r"(a[2]), "r"(a[3]), "r"(b0), "r"(b1));
}
__device__ __forceinline__ void ldsm4(unsigned r[4], uint32_t addr) {
    asm volatile("ldmatrix.sync.aligned.m8n8.x4.shared.b16 {%0,%1,%2,%3}, [%4];"
                 : "=r"(r[0]), "=r"(r[1]), "=r"(r[2]), "=r"(r[3]) : "r"(addr));
}
__device__ __forceinline__ uint32_t smem_u32(const void* p) {
    uint32_t a;
    asm("{ .reg .u64 t; cvta.to.shared.u64 t, %1; cvt.u32.u64 %0, t; }" : "=r"(a) : "l"(p));
    return a;
}
__device__ __forceinline__ void cpasync16(uint32_t dst, const void* src) {
    asm volatile("cp.async.cg.shared.global [%0], [%1], 16;" :: "r"(dst), "l"(src) : "memory");
}
__device__ __forceinline__ void cp_commit() {
    asm volatile("cp.async.commit_group;" ::: "memory");
}
__device__ __forceinline__ float sigmoidf(float v) { return 1.0f / (1.0f + expf(-v)); }
__device__ __forceinline__ uint32_t pk2h(__half a, __half b) {
    __half2 t(a, b);
    return *(uint32_t*)&t;
}

// ----------------------------- kernel: gather emb (fp16, emb half only),
// fill zpad, reset flags. z-half of g_inp is dead (K-split) and never written.
__global__ void build_inp_kernel(const int* __restrict__ x,
                                 const float* __restrict__ z,
                                 const float* __restrict__ emb) {
    size_t idx = (size_t)blockIdx.x * 256 + threadIdx.x;   // < BT*512
    if (idx < 1024) g_flags[idx] = 0u;
    if (idx < 131072) {   // zpad [128][1024]: rows<64, cols<512 = z; else 0
        int row = (int)(idx >> 10);
        int col = (int)(idx & 1023);
        float v = (row < 64 && col < 512) ? z[row * 512 + col] : 0.f;
        g_zpad[idx] = __float2half_rn(v);
    }
    int m = (int)(idx >> 9);
    int k = (int)(idx & 511);
    g_inp[(size_t)m * 1024 + k] = __float2half_rn(emb[(size_t)x[m] * 512 + k]);
}

// ----------------------------- kernel: pack weights into fp16 B-fragment order
__global__ void wpack_kernel(const float* __restrict__ Wih,
                             const float* __restrict__ Wout) {
    int idx = blockIdx.x * 256 + threadIdx.x;
    if (idx < 786432) {
        int kt = idx / 12288;
        int r  = idx % 12288;
        int strip = r >> 5, l = r & 31;
        int n = strip * 8 + (l >> 2);
        int k = kt * 16 + (l & 3) * 2;
        const float* wr = Wih + (size_t)n * GIN + k;
        uint2 v;
        v.x = pk2h(__float2half_rn(wr[0]), __float2half_rn(wr[1]));
        v.y = pk2h(__float2half_rn(wr[8]), __float2half_rn(wr[9]));
        g_wihp[idx] = v;
    } else {
        int j  = idx - 786432;
        int kt = j / 2048;
        int r  = j % 2048;
        int strip = r >> 5, l = r & 31;
        int n = strip * 8 + (l >> 2);
        int k = kt * 16 + (l & 3) * 2;
        const float* wr = Wout + (size_t)n * KOUT + k;
        uint2 v;
        v.x = pk2h(__float2half_rn(wr[0]), __float2half_rn(wr[1]));
        v.y = pk2h(__float2half_rn(wr[8]), __float2half_rn(wr[9]));
        g_woutp[j] = v;
    }
}

// ----------------------------- fp16 GEMM: C = A*W^T + bias, fp32 out
// ZROW: bias indexed per batch row (zproj[bM/4][col]) instead of bias[col].
// Single-sync pipeline: depth-2 prefetch on 3 buffers. stage(s+2) writes
// buffer (s+2)%3, whose last readers (compute(s-1)) are ordered behind this
// iteration's syncthreads -> one barrier per k-stage.
#define FSTG 34816              // A 128*144 + B 16384
template<bool CAT, bool TANH, bool ZROW>
__global__ void __launch_bounds__(256, 2)
gemm_f16(const __half* __restrict__ Ainp, const __half* __restrict__ Ahid,
         const uint2* __restrict__ Wp, const float* __restrict__ bias,
         float* __restrict__ C, int N, int K) {
    extern __shared__ char smem[];
    const uint32_t sb = smem_u32(smem);
    const int tid  = threadIdx.x;
    const int lane = tid & 31;
    const int w    = tid >> 5;
    const int wm   = w >> 1;
    const int wn   = w & 1;
    const int bN   = blockIdx.x;
    const int bM   = blockIdx.y;
    const int S    = K >> 6;
    const int NSTRIP = N >> 3;

    float acc[2][8][4];
#pragma unroll
    for (int mt = 0; mt < 2; ++mt)
#pragma unroll
        for (int nt = 0; nt < 8; ++nt)
#pragma unroll
            for (int i = 0; i < 4; ++i) acc[mt][nt][i] = 0.f;

    auto stage = [&](int s) {
        const int k0 = s * 64;
        const uint32_t base = sb + (uint32_t)(s % 3) * FSTG;
#pragma unroll
        for (int it = 0; it < 4; ++it) {
            int o = tid + it * 256;
            int row = o >> 3, seg = o & 7;
            int m = bM * 128 + row;
            const __half* srcA;
            if (CAT) {
                if (k0 < 1024)
                    srcA = Ahid + ((size_t)(m & 511) * BB + (m >> 9)) * HID + k0 + seg * 8;
                else
                    srcA = Ainp + (size_t)m * 1024 + (k0 - 1024) + seg * 8;
            } else {
                srcA = Ainp + (size_t)m * 1024 + k0 + seg * 8;
            }
            cpasync16(base + row * 144 + seg * 16, srcA);
        }
#pragma unroll
        for (int it = 0; it < 4; ++it) {
            int o = tid + it * 256;
            int ktl = o >> 8, rem = o & 255;
            const char* src = (const char*)Wp
                + ((size_t)(s * 4 + ktl) * NSTRIP + bN * 16) * 256 + rem * 16;
            cpasync16(base + 18432 + ktl * 4096 + rem * 16, src);
        }
        cp_commit();
    };

    stage(0); stage(1);

    for (int s = 0; s < S; ++s) {
        asm volatile("cp.async.wait_group 1;" ::: "memory");   // group s done
        __syncthreads();
        if (s + 2 < S) stage(s + 2);
        else cp_commit();   // keep group accounting symmetric
        const uint32_t As = sb + (uint32_t)(s % 3) * FSTG;
        const char* Bs = smem + (size_t)(s % 3) * FSTG + 18432;
        const uint32_t aAddr = As + (uint32_t)(wm * 32 + (lane & 15)) * 144 + (lane >> 4) * 16;
#pragma unroll
        for (int kt = 0; kt < 4; ++kt) {
            unsigned a[2][4];
            ldsm4(a[0], aAddr + kt * 32);
            ldsm4(a[1], aAddr + 16 * 144 + kt * 32);
#pragma unroll
            for (int nt = 0; nt < 8; ++nt) {
                uint2 Bv = *(const uint2*)(Bs + (size_t)kt * 4096
                           + (wn * 8 + nt) * 256 + lane * 8);
                mma_f16(acc[0][nt], a[0], Bv.x, Bv.y);
                mma_f16(acc[1][nt], a[1], Bv.x, Bv.y);
            }
        }
    }

    // bias row: ZROW -> per-batch-row vector (whole 128-row block is one b)
    const float* brow = ZROW ? (bias + (size_t)(bM >> 2) * N) : bias;
#pragma unroll
    for (int nt = 0; nt < 8; ++nt) {
        int col = bN * 128 + wn * 64 + nt * 8 + 2 * (lane & 3);
        float b0 = brow[col], b1 = brow[col + 1];
#pragma unroll
        for (int mt = 0; mt < 2; ++mt) {
            int row = bM * 128 + wm * 32 + mt * 16 + (lane >> 2);
            float v00 = acc[mt][nt][0] + b0;
            float v01 = acc[mt][nt][1] + b1;
            float v10 = acc[mt][nt][2] + b0;
            float v11 = acc[mt][nt][3] + b1;
            if (TANH) { v00 = tanhf(v00); v01 = tanhf(v01); v10 = tanhf(v10); v11 = tanhf(v11); }
            *(float2*)&C[(size_t)row * N + col]       = make_float2(v00, v01);
            *(float2*)&C[(size_t)(row + 8) * N + col] = make_float2(v10, v11);
        }
    }
}

// ----------------------------- GRU persistent kernel (EXACT R9/R15 — best known)
// Only delta: flag poll spins without __nanosleep (single polling warp).
#define SM_W 0u
#define SM_A 196608u
#define PBUF 8704u
#define SM_P (196608u + 8704u)
#define SMEM_GRU 222720

__global__ void __launch_bounds__(384, 1)
gru_kernel(const float* __restrict__ Whh, const float* __restrict__ bhh,
           const int* __restrict__ x, const float* __restrict__ xproj,
           __half* __restrict__ hhi) {
    extern __shared__ char smem[];
    const uint32_t sb = smem_u32(smem);
    const int tid   = threadIdx.x;
    const int wid   = tid >> 5;
    const int lane  = tid & 31;
    const int group = blockIdx.x >> 5;        // 0..3
    const int b0    = group * 16;
    const int jc    = (blockIdx.x & 31) * 32; // 32 hidden cols
    const int gate  = wid >> 2;               // 0..2
    const int kh    = (wid >> 1) & 1;         // k-half
    const int ch    = wid & 1;                // col-half
    const int s0    = gate * 4 + ch * 2;      // W strip ids
    const int s1    = s0 + 1;

    // ---- one-time: pack W_hh slice (96 rows x 1024) into fp16 B-fragments
    for (int u = tid; u < 24576; u += 384) {
        int kt = u / 384;
        int rem = u % 384;
        int strip = rem >> 5, l = rem & 31;
        int g = strip >> 2, co = (strip & 3) * 8;
        int n = jc + co + (l >> 2);
        int k = kt * 16 + (l & 3) * 2;
        const float* wr = Whh + (size_t)(g * 1024 + n) * 1024;
        uint2 v;
        v.x = pk2h(__float2half_rn(wr[k]),     __float2half_rn(wr[k + 1]));
        v.y = pk2h(__float2half_rn(wr[k + 8]), __float2half_rn(wr[k + 9]));
        *(uint2*)(smem + SM_W + (size_t)(kt * 12 + strip) * 256 + (size_t)l * 8) = v;
    }
    __syncthreads();

    // ---- epilogue thread setup: tid<128, each owns (batch row, 4 cols)
    const int erow = tid >> 3;                // 0..15
    const int ec4  = (tid & 7) * 4;           // 0,4,..28
    const int eb   = b0 + erow;
    float hp[4] = {0.f, 0.f, 0.f, 0.f};
    float br_[4], bu_[4], bn_[4];
    if (tid < 128) {
#pragma unroll
        for (int j = 0; j < 4; ++j) {
            br_[j] = bhh[jc + ec4 + j];
            bu_[j] = bhh[1024 + jc + ec4 + j];
            bn_[j] = bhh[2048 + jc + ec4 + j];
        }
    }

    for (int t = 0; t < TT; ++t) {
        // ---- epilogue operand prefetch (fp32 xproj)
        int xtok = 0;
        float4 xr, xu, xn;
        if (tid < 128) {
            xtok = x[eb * TT + t];
            const float* xb = xproj + ((size_t)eb * TT + t) * H3 + jc + ec4;
            xr = *(const float4*)xb;
            xu = *(const float4*)(xb + 1024);
            xn = *(const float4*)(xb + 2048);
        }

        if (t > 0) {
            // coarse group-flag wait: warp 0 only, one flag per lane, hard spin
            if (wid == 0) {
                const unsigned* f = &g_flags[(group * 32 + lane) * 8];
                for (;;) {
                    unsigned v;
                    asm volatile("ld.acquire.gpu.global.u32 %0, [%1];" : "=r"(v) : "l"(f));
                    if (__all_sync(0xffffffffu, v >= (unsigned)t)) break;
                }
            }
            __syncthreads();

            // stage pair i: chunks {i, i+4} of h(t-1)
            auto stage = [&](int i) {
                if (tid < 256) {
                    int row = tid >> 4, seg = tid & 15;
                    const __half* src = hhi + ((size_t)(t - 1) * BB + b0 + row) * HID + seg * 8;
                    uint32_t dst = sb + SM_A + (uint32_t)(i % 3) * PBUF
                                 + (uint32_t)row * 272 + seg * 16;
                    cpasync16(dst,        src + i * 128);
                    cpasync16(dst + 4352, src + (i + 4) * 128);
                }
                cp_commit();
            };

            float acc[2][2][4] = {};   // [ntile][parity][4]
            stage(0); stage(1);
            for (int i = 0; i < 4; ++i) {
                if (i < 3) asm volatile("cp.async.wait_group 1;" ::: "memory");
                else       asm volatile("cp.async.wait_group 0;" ::: "memory");
                __syncthreads();
                if (i < 2) stage(i + 2);
                const uint32_t ah = sb + SM_A + (uint32_t)(i % 3) * PBUF
                                  + (uint32_t)kh * 4352
                                  + (uint32_t)(lane & 15) * 272 + (lane >> 4) * 16;
                const int ktg0 = kh * 32 + i * 8;
#pragma unroll
                for (int kt = 0; kt < 8; ++kt) {
                    unsigned aF[4];
                    ldsm4(aF, ah + kt * 32);
                    uint2 B0 = *(const uint2*)(smem + SM_W
                               + (size_t)((ktg0 + kt) * 12 + s0) * 256 + (size_t)lane * 8);
                    uint2 B1 = *(const uint2*)(smem + SM_W
                               + (size_t)((ktg0 + kt) * 12 + s1) * 256 + (size_t)lane * 8);
                    const int p = kt & 1;
                    mma_f16(acc[0][p], aF, B0.x, B0.y);
                    mma_f16(acc[1][p], aF, B1.x, B1.y);
                }
            }
            // preact partial write: [(gate*2+kh)*16 + r][36 floats]
            // (aliases buffer 1: last read iter 1, ordered before sync(3))
            {
                int r  = lane >> 2;
                int cb = ch * 16 + 2 * (lane & 3);
#pragma unroll
                for (int nt = 0; nt < 2; ++nt) {
                    float d0 = acc[nt][0][0] + acc[nt][1][0];
                    float d1 = acc[nt][0][1] + acc[nt][1][1];
                    float d2 = acc[nt][0][2] + acc[nt][1][2];
                    float d3 = acc[nt][0][3] + acc[nt][1][3];
                    int col = cb + nt * 8;
                    *(float2*)(smem + SM_P
                        + (size_t)(((gate * 2 + kh) * 16 + r) * 36 + col) * 4)
                        = make_float2(d0, d1);
                    *(float2*)(smem + SM_P
                        + (size_t)(((gate * 2 + kh) * 16 + r + 8) * 36 + col) * 4)
                        = make_float2(d2, d3);
                }
            }
        }
        __syncthreads();

        // ---- epilogue: 128 threads, (row, 4 cols) each
        if (tid < 128) {
            float dr[4] = {}, du[4] = {}, dn[4] = {};
            if (t > 0) {
#pragma unroll
                for (int g = 0; g < 3; ++g) {
                    float4 a = *(const float4*)(smem + SM_P
                               + (size_t)((g * 2 + 0) * 16 + erow) * 144 + ec4 * 4);
                    float4 b = *(const float4*)(smem + SM_P
                               + (size_t)((g * 2 + 1) * 16 + erow) * 144 + ec4 * 4);
                    float* d = (g == 0) ? dr : (g == 1 ? du : dn);
                    d[0] = a.x + b.x; d[1] = a.y + b.y;
                    d[2] = a.z + b.z; d[3] = a.w + b.w;
                }
            }
            float xrv[4] = {xr.x, xr.y, xr.z, xr.w};
            float xuv[4] = {xu.x, xu.y, xu.z, xu.w};
            float xnv[4] = {xn.x, xn.y, xn.z, xn.w};
            const bool msk = (xtok == 0);   // PAD
            float hv[4];
#pragma unroll
            for (int j = 0; j < 4; ++j) {
                float rr = sigmoidf(xrv[j] + dr[j] + br_[j]);
                float uu = sigmoidf(xuv[j] + du[j] + bu_[j]);
                float nn = tanhf(xnv[j] + rr * (dn[j] + bn_[j]));
                float h  = (1.f - uu) * nn + uu * hp[j];
                hv[j] = msk ? hp[j] : h;
                hp[j] = hv[j];
            }
            uint2 uh;
            uh.x = pk2h(__float2half_rn(hv[0]), __float2half_rn(hv[1]));
            uh.y = pk2h(__float2half_rn(hv[2]), __float2half_rn(hv[3]));
            *(uint2*)(hhi + ((size_t)t * BB + eb) * HID + jc + ec4) = uh;
        }
        __syncthreads();

        // ---- release (bar gives intra-CTA HB; gpu-scope release publishes)
        if (tid == 0) {
            asm volatile("st.release.gpu.global.u32 [%0], %1;"
                         :: "l"(&g_flags[blockIdx.x * 8]), "r"((unsigned)(t + 1)) : "memory");
        }
    }
}

// ----------------------------- launch
extern "C" void kernel_launch(void* const* d_in, const int* in_sizes, int n_in,
                              void* d_out, int out_size) {
    const int*   x     = (const int*)d_in[0];
    const float* z     = (const float*)d_in[1];
    const float* emb   = (const float*)d_in[2];
    const float* W_ih  = (const float*)d_in[3];
    const float* b_ih  = (const float*)d_in[4];
    const float* W_hh  = (const float*)d_in[5];
    const float* b_hh  = (const float*)d_in[6];
    const float* W_out = (const float*)d_in[7];
    const float* b_out = (const float*)d_in[8];
    float* out = (float*)d_out;

    float *xproj_p, *zproj_p;
    __half *inp_p, *zpad_p, *hhi_p;
    uint2 *wihp_p, *woutp_p;
    cudaGetSymbolAddress((void**)&inp_p,   g_inp);
    cudaGetSymbolAddress((void**)&zpad_p,  g_zpad);
    cudaGetSymbolAddress((void**)&zproj_p, g_zproj);
    cudaGetSymbolAddress((void**)&xproj_p, g_xproj);
    cudaGetSymbolAddress((void**)&hhi_p,   g_hhi);
    cudaGetSymbolAddress((void**)&wihp_p,  g_wihp);
    cudaGetSymbolAddress((void**)&woutp_p, g_woutp);

    // 1. build inp (fp16 emb half only), zpad, reset barrier flags
    build_inp_kernel<<<(unsigned)((size_t)BT * 512 / 256), 256>>>(x, z, emb);

    // 2. pack weights into fp16 fragment order
    wpack_kernel<<<3840, 256>>>(W_ih, W_out);

    // 3a. zproj = z @ W_ih[:,512:]^T + b_ih   [64(pad 128) x 3072], K=512
    {
        cudaFuncSetAttribute(gemm_f16<false, false, false>,
                             cudaFuncAttributeMaxDynamicSharedMemorySize, 3 * FSTG);
        dim3 grid(H3 / 128, 1);
        gemm_f16<false, false, false><<<grid, 256, 3 * FSTG>>>(
            zpad_p, nullptr, wihp_p + 393216, b_ih, zproj_p, H3, 512);
    }

    // 3b. xproj = emb @ W_ih[:,:512]^T + zproj[b]   [32768 x 3072], K=512
    {
        cudaFuncSetAttribute(gemm_f16<false, false, true>,
                             cudaFuncAttributeMaxDynamicSharedMemorySize, 3 * FSTG);
        dim3 grid(H3 / 128, BT / 128);
        gemm_f16<false, false, true><<<grid, 256, 3 * FSTG>>>(
            inp_p, nullptr, wihp_p, zproj_p, xproj_p, H3, 512);
    }

    // 4. GRU recurrence: 4 independent batch groups x 32 CTAs (R9-exact)
    {
        cudaFuncSetAttribute(gru_kernel,
                             cudaFuncAttributeMaxDynamicSharedMemorySize, SMEM_GRU);
        gru_kernel<<<128, 384, SMEM_GRU>>>(W_hh, b_hh, x, xproj_p, hhi_p);
    }

    // 5. logits = tanh([hidden|emb] @ W_out^T + b_out)   [32768 x 512], K=1536
    {
        cudaFuncSetAttribute(gemm_f16<true, true, false>,
                             cudaFuncAttributeMaxDynamicSharedMemorySize, 3 * FSTG);
        dim3 grid(NIN / 128, BT / 128);
        gemm_f16<true, true, false><<<grid, 256, 3 * FSTG>>>(
            inp_p, hhi_p, woutp_p, b_out, out, NIN, KOUT);
    }
}